// round 1
// baseline (speedup 1.0000x reference)
#include <cuda_runtime.h>
#include <cstdint>

#define T_TOK 32768
#define N_CODE 8192
#define D_DIM 64
#define NSEG 16
#define SEGSZ 512          // codes per segment
#define CHUNK 128          // codes per smem tile
#define TILE_T 128         // tokens per block tile

#define ZQ_OFF   0
#define LOSS_OFF 2097152
#define IDX_OFF  2097153

// ---------------- scratch (device globals; no allocation allowed) -------------
__device__ __align__(16) float g_zfT[D_DIM * T_TOK];     // [d][t] normalized tokens
__device__ float g_zsq[T_TOK];                            // ||zf||^2 per token
__device__ __align__(16) float g_en[N_CODE * D_DIM];      // [n][d] normalized codes
__device__ __align__(16) float g_enT[D_DIM * N_CODE];     // [d][n]
__device__ __align__(16) float g_c2[N_CODE];              // ||en||^2
__device__ unsigned long long g_segbest[NSEG * T_TOK];    // packed (score|idx)
__device__ int g_idx[T_TOK];
__device__ double g_losspart[4096];

// ---------------- helpers -----------------------------------------------------
__device__ __forceinline__ unsigned long long pk2(float x, float y) {
    unsigned long long r;
    asm("mov.b64 %0, {%1, %2};" : "=l"(r) : "f"(x), "f"(y));
    return r;
}
__device__ __forceinline__ unsigned long long f2fma(unsigned long long a,
                                                    unsigned long long b,
                                                    unsigned long long c) {
    unsigned long long d;
    asm("fma.rn.f32x2 %0, %1, %2, %3;" : "=l"(d) : "l"(a), "l"(b), "l"(c));
    return d;
}
__device__ __forceinline__ void upk(unsigned long long v, float& lo, float& hi) {
    asm("mov.b64 {%0, %1}, %2;" : "=f"(lo), "=f"(hi) : "l"(v));
}
__device__ __forceinline__ unsigned orderU(float s) {
    unsigned u = __float_as_uint(s);
    return (u & 0x80000000u) ? ~u : (u | 0x80000000u);
}
__device__ __forceinline__ float warp_sum(float v) {
    #pragma unroll
    for (int o = 16; o; o >>= 1) v += __shfl_xor_sync(0xffffffffu, v, o);
    return v;
}

// ---------------- 1) codebook prep: en, enT, c2 -------------------------------
__global__ void prep_codebook(const float* __restrict__ cb) {
    int w = threadIdx.x >> 5, lane = threadIdx.x & 31;
    int c = blockIdx.x * 8 + w;
    float v0 = cb[c * 64 + lane];
    float v1 = cb[c * 64 + 32 + lane];
    float ss = warp_sum(v0 * v0 + v1 * v1);
    float den = fmaxf(__fsqrt_rn(ss), 1e-12f);
    float e0 = __fdiv_rn(v0, den);
    float e1 = __fdiv_rn(v1, den);
    float c2 = warp_sum(e0 * e0 + e1 * e1);
    g_en[c * 64 + lane] = e0;
    g_en[c * 64 + 32 + lane] = e1;
    g_enT[lane * N_CODE + c] = e0;
    g_enT[(lane + 32) * N_CODE + c] = e1;
    if (lane == 0) g_c2[c] = c2;
}

// ---------------- 2) token prep: zfT (transposed), zsq ------------------------
__global__ void prep_z(const float* __restrict__ z) {
    __shared__ float sZ[64][65];
    int tid = threadIdx.x;
    int t0 = blockIdx.x * 64;
    #pragma unroll
    for (int i = 0; i < 16; i++) {
        int f = tid + i * 256;
        sZ[f >> 6][f & 63] = z[t0 * 64 + f];
    }
    __syncthreads();
    int w = tid >> 5, lane = tid & 31;
    #pragma unroll
    for (int r = 0; r < 8; r++) {
        int tt = w * 8 + r;
        float v0 = sZ[tt][lane], v1 = sZ[tt][lane + 32];
        float ss = warp_sum(v0 * v0 + v1 * v1);
        float den = fmaxf(__fsqrt_rn(ss), 1e-12f);
        float zf0 = __fdiv_rn(v0, den);
        float zf1 = __fdiv_rn(v1, den);
        float q = warp_sum(zf0 * zf0 + zf1 * zf1);
        sZ[tt][lane] = zf0;
        sZ[tt][lane + 32] = zf1;
        if (lane == 0) g_zsq[t0 + tt] = q;
    }
    __syncthreads();
    #pragma unroll
    for (int i = 0; i < 16; i++) {
        int f = tid + i * 256;
        int d = f >> 6, tt = f & 63;
        g_zfT[d * T_TOK + t0 + tt] = sZ[tt][d];
    }
}

// ---------------- 3) main GEMM + argmin ---------------------------------------
// grid: (NSEG, T_TOK/TILE_T). 256 threads, 16x16, 8x8 micro-tile, f32x2 packed.
__global__ __launch_bounds__(256) void vq_main() {
    extern __shared__ float sm[];
    float* sZ = sm;                     // [64][128]
    float* sE = sm + 64 * 128;          // [64][128]
    float* sC = sm + 2 * 64 * 128;      // [128]

    int tid = threadIdx.x;
    int tx = tid & 15, ty = tid >> 4;
    int seg = blockIdx.x;
    int tok0 = blockIdx.y * TILE_T;

    // load token tile (transposed layout already in gmem)
    #pragma unroll
    for (int i = 0; i < 8; i++) {
        int f = tid + i * 256;          // float4 index
        int k = f >> 5;
        int c = (f & 31) << 2;
        *(float4*)&sZ[k * 128 + c] = *(const float4*)&g_zfT[k * T_TOK + tok0 + c];
    }
    float zsqf[8];
    #pragma unroll
    for (int i = 0; i < 8; i++) zsqf[i] = g_zsq[tok0 + ty * 8 + i];

    float bestS[8];
    int bestJ[8];
    #pragma unroll
    for (int i = 0; i < 8; i++) { bestS[i] = 3.402823466e+38f; bestJ[i] = 0; }

    for (int chunk = 0; chunk < 4; chunk++) {
        int cb0 = seg * SEGSZ + chunk * CHUNK;
        // load code tile + c2
        #pragma unroll
        for (int i = 0; i < 8; i++) {
            int f = tid + i * 256;
            int k = f >> 5;
            int c = (f & 31) << 2;
            *(float4*)&sE[k * 128 + c] = *(const float4*)&g_enT[k * N_CODE + cb0 + c];
        }
        if (tid < 32) *(float4*)&sC[tid * 4] = *(const float4*)&g_c2[cb0 + tid * 4];
        __syncthreads();

        unsigned long long acc[8][4];
        #pragma unroll
        for (int j = 0; j < 8; j++)
            #pragma unroll
            for (int p = 0; p < 4; p++) acc[j][p] = 0ull;

        #pragma unroll 8
        for (int k = 0; k < 64; k++) {
            union { float4 v; unsigned long long u[2]; } za, zb;
            za.v = *(const float4*)&sZ[k * 128 + ty * 8];
            zb.v = *(const float4*)&sZ[k * 128 + ty * 8 + 4];
            unsigned long long a[4] = { za.u[0], za.u[1], zb.u[0], zb.u[1] };
            float4 ea = *(const float4*)&sE[k * 128 + tx * 8];
            float4 eb = *(const float4*)&sE[k * 128 + tx * 8 + 4];
            float e[8] = { ea.x, ea.y, ea.z, ea.w, eb.x, eb.y, eb.z, eb.w };
            #pragma unroll
            for (int j = 0; j < 8; j++) {
                unsigned long long bj = pk2(e[j], e[j]);
                #pragma unroll
                for (int p = 0; p < 4; p++)
                    acc[j][p] = f2fma(a[p], bj, acc[j][p]);
            }
        }

        // epilogue: score = (zsq + c2) - 2*dot, running argmin
        float c2f[8];
        #pragma unroll
        for (int j = 0; j < 8; j++) c2f[j] = sC[tx * 8 + j];
        #pragma unroll
        for (int j = 0; j < 8; j++) {
            int jg = cb0 + tx * 8 + j;
            #pragma unroll
            for (int p = 0; p < 4; p++) {
                float dlo, dhi;
                upk(acc[j][p], dlo, dhi);
                int i0 = 2 * p, i1 = 2 * p + 1;
                float s0 = (zsqf[i0] + c2f[j]) - 2.0f * dlo;
                float s1 = (zsqf[i1] + c2f[j]) - 2.0f * dhi;
                if (s0 < bestS[i0]) { bestS[i0] = s0; bestJ[i0] = jg; }
                if (s1 < bestS[i1]) { bestS[i1] = s1; bestJ[i1] = jg; }
            }
        }
        __syncthreads();
    }

    // reduce across the 16 tx-threads sharing each token row (u64 min => ties
    // resolve to the smallest code index, matching argmin-first semantics)
    #pragma unroll
    for (int i = 0; i < 8; i++) {
        unsigned long long key =
            ((unsigned long long)orderU(bestS[i]) << 32) | (unsigned)bestJ[i];
        #pragma unroll
        for (int o = 8; o; o >>= 1) {
            unsigned long long v = __shfl_xor_sync(0xffffffffu, key, o);
            if (v < key) key = v;
        }
        if (tx == 0)
            g_segbest[seg * T_TOK + tok0 + ty * 8 + i] = key;
    }
}

// ---------------- 4) combine segments -> idx ----------------------------------
__global__ void vq_combine(float* __restrict__ out) {
    int t = blockIdx.x * 256 + threadIdx.x;
    unsigned long long m = g_segbest[t];
    #pragma unroll
    for (int s = 1; s < NSEG; s++) {
        unsigned long long v = g_segbest[s * T_TOK + t];
        if (v < m) m = v;
    }
    int idx = (int)(m & 0xffffffffull);
    g_idx[t] = idx;
    out[IDX_OFF + t] = (float)idx;
}

// ---------------- 5) gather z_qnorm + loss partials ---------------------------
__global__ void vq_gather(const float* __restrict__ z, float* __restrict__ out) {
    __shared__ float wsum[8];
    int tid = threadIdx.x, w = tid >> 5, lane = tid & 31;
    int t = blockIdx.x * 8 + w;
    int idx = g_idx[t];
    float e0 = g_en[idx * 64 + lane];
    float e1 = g_en[idx * 64 + 32 + lane];
    float z0 = z[t * 64 + lane];
    float z1 = z[t * 64 + 32 + lane];
    float ss = warp_sum(z0 * z0 + z1 * z1);
    float den = fmaxf(__fsqrt_rn(ss), 1e-12f);
    float zf0 = __fdiv_rn(z0, den);
    float zf1 = __fdiv_rn(z1, den);
    float d0 = e0 - zf0, d1 = e1 - zf1;
    float ls = warp_sum(d0 * d0 + d1 * d1);
    out[ZQ_OFF + t * 64 + lane] = e0;
    out[ZQ_OFF + t * 64 + 32 + lane] = e1;
    if (lane == 0) wsum[w] = ls;
    __syncthreads();
    if (tid == 0) {
        double s = 0.0;
        #pragma unroll
        for (int i = 0; i < 8; i++) s += (double)wsum[i];
        g_losspart[blockIdx.x] = s;
    }
}

// ---------------- 6) finalize loss (deterministic tree) -----------------------
__global__ void vq_loss(float* __restrict__ out) {
    __shared__ double sh[256];
    int tid = threadIdx.x;
    double s = 0.0;
    for (int i = 0; i < 16; i++) s += g_losspart[tid + i * 256];
    sh[tid] = s;
    __syncthreads();
    for (int o = 128; o; o >>= 1) {
        if (tid < o) sh[tid] += sh[tid + o];
        __syncthreads();
    }
    if (tid == 0) out[LOSS_OFF] = (float)(sh[0] * 1.25 / 2097152.0);
}

// ---------------- launch ------------------------------------------------------
extern "C" void kernel_launch(void* const* d_in, const int* in_sizes, int n_in,
                              void* d_out, int out_size) {
    const float* z  = (const float*)d_in[0];
    const float* cb = (const float*)d_in[1];
    if (n_in >= 2 && in_sizes[0] == N_CODE * D_DIM && in_sizes[1] == T_TOK * D_DIM) {
        const float* tmp = z; z = cb; cb = tmp;   // defensive: swap if order differs
    }
    float* out = (float*)d_out;

    const int smemB = (2 * 64 * 128 + 128) * (int)sizeof(float);  // 66048
    cudaStreamCaptureStatus st = cudaStreamCaptureStatusNone;
    cudaStreamIsCapturing(0, &st);
    if (st == cudaStreamCaptureStatusNone) {
        cudaFuncSetAttribute(vq_main, cudaFuncAttributeMaxDynamicSharedMemorySize, smemB);
    }

    prep_codebook<<<N_CODE / 8, 256>>>(cb);
    prep_z<<<T_TOK / 64, 256>>>(z);
    vq_main<<<dim3(NSEG, T_TOK / TILE_T), 256, smemB>>>();
    vq_combine<<<T_TOK / 256, 256>>>(out);
    vq_gather<<<T_TOK / 8, 256>>>(z, out);
    vq_loss<<<1, 256>>>(out);
}

// round 2
// speedup vs baseline: 1.0000x; 1.0000x over previous
#include <cuda_runtime.h>
#include <cstdint>

#define T_TOK 32768
#define N_CODE 8192
#define D_DIM 64
#define NSEG 16
#define SEGSZ 512          // codes per segment
#define CHUNK 128          // codes per smem tile
#define TILE_T 128         // tokens per block tile

#define ZQ_OFF   0
#define LOSS_OFF 2097152
#define IDX_OFF  2097153

// ---------------- scratch (device globals; no allocation allowed) -------------
__device__ __align__(16) float g_zfT[D_DIM * T_TOK];     // [d][t] normalized tokens
__device__ float g_zsq[T_TOK];                            // ||zf||^2 per token
__device__ __align__(16) float g_en[N_CODE * D_DIM];      // [n][d] normalized codes
__device__ __align__(16) float g_enT[D_DIM * N_CODE];     // [d][n]
__device__ __align__(16) float g_c2[N_CODE];              // ||en||^2
__device__ unsigned long long g_segbest[NSEG * T_TOK];    // packed (score|idx)
__device__ int g_idx[T_TOK];
__device__ double g_losspart[4096];

// ---------------- helpers -----------------------------------------------------
__device__ __forceinline__ unsigned long long pk2(float x, float y) {
    unsigned long long r;
    asm("mov.b64 %0, {%1, %2};" : "=l"(r) : "f"(x), "f"(y));
    return r;
}
__device__ __forceinline__ unsigned long long f2fma(unsigned long long a,
                                                    unsigned long long b,
                                                    unsigned long long c) {
    unsigned long long d;
    asm("fma.rn.f32x2 %0, %1, %2, %3;" : "=l"(d) : "l"(a), "l"(b), "l"(c));
    return d;
}
__device__ __forceinline__ void upk(unsigned long long v, float& lo, float& hi) {
    asm("mov.b64 {%0, %1}, %2;" : "=f"(lo), "=f"(hi) : "l"(v));
}
__device__ __forceinline__ unsigned orderU(float s) {
    unsigned u = __float_as_uint(s);
    return (u & 0x80000000u) ? ~u : (u | 0x80000000u);
}
__device__ __forceinline__ float warp_sum(float v) {
    #pragma unroll
    for (int o = 16; o; o >>= 1) v += __shfl_xor_sync(0xffffffffu, v, o);
    return v;
}

// ---------------- 1) codebook prep: en, enT, c2 -------------------------------
__global__ void prep_codebook(const float* __restrict__ cb) {
    int w = threadIdx.x >> 5, lane = threadIdx.x & 31;
    int c = blockIdx.x * 8 + w;
    float v0 = cb[c * 64 + lane];
    float v1 = cb[c * 64 + 32 + lane];
    float ss = warp_sum(v0 * v0 + v1 * v1);
    float den = fmaxf(__fsqrt_rn(ss), 1e-12f);
    float e0 = __fdiv_rn(v0, den);
    float e1 = __fdiv_rn(v1, den);
    float c2 = warp_sum(e0 * e0 + e1 * e1);
    g_en[c * 64 + lane] = e0;
    g_en[c * 64 + 32 + lane] = e1;
    g_enT[lane * N_CODE + c] = e0;
    g_enT[(lane + 32) * N_CODE + c] = e1;
    if (lane == 0) g_c2[c] = c2;
}

// ---------------- 2) token prep: zfT (transposed), zsq ------------------------
__global__ void prep_z(const float* __restrict__ z) {
    __shared__ float sZ[64][65];
    int tid = threadIdx.x;
    int t0 = blockIdx.x * 64;
    #pragma unroll
    for (int i = 0; i < 16; i++) {
        int f = tid + i * 256;
        sZ[f >> 6][f & 63] = z[t0 * 64 + f];
    }
    __syncthreads();
    int w = tid >> 5, lane = tid & 31;
    #pragma unroll
    for (int r = 0; r < 8; r++) {
        int tt = w * 8 + r;
        float v0 = sZ[tt][lane], v1 = sZ[tt][lane + 32];
        float ss = warp_sum(v0 * v0 + v1 * v1);
        float den = fmaxf(__fsqrt_rn(ss), 1e-12f);
        float zf0 = __fdiv_rn(v0, den);
        float zf1 = __fdiv_rn(v1, den);
        float q = warp_sum(zf0 * zf0 + zf1 * zf1);
        sZ[tt][lane] = zf0;
        sZ[tt][lane + 32] = zf1;
        if (lane == 0) g_zsq[t0 + tt] = q;
    }
    __syncthreads();
    #pragma unroll
    for (int i = 0; i < 16; i++) {
        int f = tid + i * 256;
        int d = f >> 6, tt = f & 63;
        g_zfT[d * T_TOK + t0 + tt] = sZ[tt][d];
    }
}

// ---------------- 3) main GEMM + argmin ---------------------------------------
// grid: (NSEG, T_TOK/TILE_T). 256 threads, 16x16, 8x8 micro-tile, f32x2 packed.
__global__ __launch_bounds__(256) void vq_main() {
    extern __shared__ float sm[];
    float* sZ = sm;                     // [64][128]
    float* sE = sm + 64 * 128;          // [64][128]
    float* sC = sm + 2 * 64 * 128;      // [128]

    int tid = threadIdx.x;
    int tx = tid & 15, ty = tid >> 4;
    int seg = blockIdx.x;
    int tok0 = blockIdx.y * TILE_T;

    // load token tile (transposed layout already in gmem)
    #pragma unroll
    for (int i = 0; i < 8; i++) {
        int f = tid + i * 256;          // float4 index
        int k = f >> 5;
        int c = (f & 31) << 2;
        *(float4*)&sZ[k * 128 + c] = *(const float4*)&g_zfT[k * T_TOK + tok0 + c];
    }
    float zsqf[8];
    #pragma unroll
    for (int i = 0; i < 8; i++) zsqf[i] = g_zsq[tok0 + ty * 8 + i];

    float bestS[8];
    int bestJ[8];
    #pragma unroll
    for (int i = 0; i < 8; i++) { bestS[i] = 3.402823466e+38f; bestJ[i] = 0; }

    for (int chunk = 0; chunk < 4; chunk++) {
        int cb0 = seg * SEGSZ + chunk * CHUNK;
        // load code tile + c2
        #pragma unroll
        for (int i = 0; i < 8; i++) {
            int f = tid + i * 256;
            int k = f >> 5;
            int c = (f & 31) << 2;
            *(float4*)&sE[k * 128 + c] = *(const float4*)&g_enT[k * N_CODE + cb0 + c];
        }
        if (tid < 32) *(float4*)&sC[tid * 4] = *(const float4*)&g_c2[cb0 + tid * 4];
        __syncthreads();

        unsigned long long acc[8][4];
        #pragma unroll
        for (int j = 0; j < 8; j++)
            #pragma unroll
            for (int p = 0; p < 4; p++) acc[j][p] = 0ull;

        #pragma unroll 8
        for (int k = 0; k < 64; k++) {
            union { float4 v; unsigned long long u[2]; } za, zb;
            za.v = *(const float4*)&sZ[k * 128 + ty * 8];
            zb.v = *(const float4*)&sZ[k * 128 + ty * 8 + 4];
            unsigned long long a[4] = { za.u[0], za.u[1], zb.u[0], zb.u[1] };
            float4 ea = *(const float4*)&sE[k * 128 + tx * 8];
            float4 eb = *(const float4*)&sE[k * 128 + tx * 8 + 4];
            float e[8] = { ea.x, ea.y, ea.z, ea.w, eb.x, eb.y, eb.z, eb.w };
            #pragma unroll
            for (int j = 0; j < 8; j++) {
                unsigned long long bj = pk2(e[j], e[j]);
                #pragma unroll
                for (int p = 0; p < 4; p++)
                    acc[j][p] = f2fma(a[p], bj, acc[j][p]);
            }
        }

        // epilogue: score = (zsq + c2) - 2*dot, running argmin
        float c2f[8];
        #pragma unroll
        for (int j = 0; j < 8; j++) c2f[j] = sC[tx * 8 + j];
        #pragma unroll
        for (int j = 0; j < 8; j++) {
            int jg = cb0 + tx * 8 + j;
            #pragma unroll
            for (int p = 0; p < 4; p++) {
                float dlo, dhi;
                upk(acc[j][p], dlo, dhi);
                int i0 = 2 * p, i1 = 2 * p + 1;
                float s0 = (zsqf[i0] + c2f[j]) - 2.0f * dlo;
                float s1 = (zsqf[i1] + c2f[j]) - 2.0f * dhi;
                if (s0 < bestS[i0]) { bestS[i0] = s0; bestJ[i0] = jg; }
                if (s1 < bestS[i1]) { bestS[i1] = s1; bestJ[i1] = jg; }
            }
        }
        __syncthreads();
    }

    // reduce across the 16 tx-threads sharing each token row (u64 min => ties
    // resolve to the smallest code index, matching argmin-first semantics)
    #pragma unroll
    for (int i = 0; i < 8; i++) {
        unsigned long long key =
            ((unsigned long long)orderU(bestS[i]) << 32) | (unsigned)bestJ[i];
        #pragma unroll
        for (int o = 8; o; o >>= 1) {
            unsigned long long v = __shfl_xor_sync(0xffffffffu, key, o);
            if (v < key) key = v;
        }
        if (tx == 0)
            g_segbest[seg * T_TOK + tok0 + ty * 8 + i] = key;
    }
}

// ---------------- 4) combine segments -> idx ----------------------------------
__global__ void vq_combine(float* __restrict__ out) {
    int t = blockIdx.x * 256 + threadIdx.x;
    unsigned long long m = g_segbest[t];
    #pragma unroll
    for (int s = 1; s < NSEG; s++) {
        unsigned long long v = g_segbest[s * T_TOK + t];
        if (v < m) m = v;
    }
    int idx = (int)(m & 0xffffffffull);
    g_idx[t] = idx;
    out[IDX_OFF + t] = (float)idx;
}

// ---------------- 5) gather z_qnorm + loss partials ---------------------------
__global__ void vq_gather(const float* __restrict__ z, float* __restrict__ out) {
    __shared__ float wsum[8];
    int tid = threadIdx.x, w = tid >> 5, lane = tid & 31;
    int t = blockIdx.x * 8 + w;
    int idx = g_idx[t];
    float e0 = g_en[idx * 64 + lane];
    float e1 = g_en[idx * 64 + 32 + lane];
    float z0 = z[t * 64 + lane];
    float z1 = z[t * 64 + 32 + lane];
    float ss = warp_sum(z0 * z0 + z1 * z1);
    float den = fmaxf(__fsqrt_rn(ss), 1e-12f);
    float zf0 = __fdiv_rn(z0, den);
    float zf1 = __fdiv_rn(z1, den);
    float d0 = e0 - zf0, d1 = e1 - zf1;
    float ls = warp_sum(d0 * d0 + d1 * d1);
    out[ZQ_OFF + t * 64 + lane] = e0;
    out[ZQ_OFF + t * 64 + 32 + lane] = e1;
    if (lane == 0) wsum[w] = ls;
    __syncthreads();
    if (tid == 0) {
        double s = 0.0;
        #pragma unroll
        for (int i = 0; i < 8; i++) s += (double)wsum[i];
        g_losspart[blockIdx.x] = s;
    }
}

// ---------------- 6) finalize loss (deterministic tree) -----------------------
__global__ void vq_loss(float* __restrict__ out) {
    __shared__ double sh[256];
    int tid = threadIdx.x;
    double s = 0.0;
    for (int i = 0; i < 16; i++) s += g_losspart[tid + i * 256];
    sh[tid] = s;
    __syncthreads();
    for (int o = 128; o; o >>= 1) {
        if (tid < o) sh[tid] += sh[tid + o];
        __syncthreads();
    }
    if (tid == 0) out[LOSS_OFF] = (float)(sh[0] * 1.25 / 2097152.0);
}

// ---------------- launch ------------------------------------------------------
extern "C" void kernel_launch(void* const* d_in, const int* in_sizes, int n_in,
                              void* d_out, int out_size) {
    const float* z  = (const float*)d_in[0];
    const float* cb = (const float*)d_in[1];
    if (n_in >= 2 && in_sizes[0] == N_CODE * D_DIM && in_sizes[1] == T_TOK * D_DIM) {
        const float* tmp = z; z = cb; cb = tmp;   // defensive: swap if order differs
    }
    float* out = (float*)d_out;

    const int smemB = (2 * 64 * 128 + 128) * (int)sizeof(float);  // 66048
    cudaStreamCaptureStatus st = cudaStreamCaptureStatusNone;
    cudaStreamIsCapturing(0, &st);
    if (st == cudaStreamCaptureStatusNone) {
        cudaFuncSetAttribute(vq_main, cudaFuncAttributeMaxDynamicSharedMemorySize, smemB);
    }

    prep_codebook<<<N_CODE / 8, 256>>>(cb);
    prep_z<<<T_TOK / 64, 256>>>(z);
    vq_main<<<dim3(NSEG, T_TOK / TILE_T), 256, smemB>>>();
    vq_combine<<<T_TOK / 256, 256>>>(out);
    vq_gather<<<T_TOK / 8, 256>>>(z, out);
    vq_loss<<<1, 256>>>(out);
}